// round 2
// baseline (speedup 1.0000x reference)
#include <cuda_runtime.h>

// Problem constants (shapes fixed by the dataset)
#define NNODES 100000
#define NEDGES 1600000
#define NGRAPH 128
#define HDIM   128
#define FDIM   64
#define LN_EPS 1e-5f

// ---------------- scratch (device globals; no allocations allowed) ----------
__device__ float g_dinv[NNODES];                    // deg -> rsqrt(deg), in place
__device__ float g_norm[NEDGES];                    // dinv[src]*dinv[dst]
__device__ float g_bufa[(size_t)NNODES * HDIM];     // agg buffers (conv1 uses first N*64)
__device__ float g_bufb[(size_t)NNODES * HDIM];
__device__ float g_gsum[NGRAPH * HDIM];
__device__ int   g_gcnt[NGRAPH];

// ---------------- degree / norm ----------------
__global__ void k_init_deg(float* deg, int n) {
    int i = blockIdx.x * blockDim.x + threadIdx.x;
    if (i < n) deg[i] = 1.0f;                       // self-loop
}
__global__ void k_count_deg(const int* __restrict__ dst, float* deg, int e) {
    int i = blockIdx.x * blockDim.x + threadIdx.x;
    if (i < e) atomicAdd(&deg[dst[i]], 1.0f);
}
__global__ void k_dinv(float* deg, int n) {
    int i = blockIdx.x * blockDim.x + threadIdx.x;
    if (i < n) deg[i] = rsqrtf(deg[i]);             // deg >= 1 always
}
__global__ void k_norm(const int* __restrict__ src, const int* __restrict__ dst,
                       const float* __restrict__ dinv, float* __restrict__ nrm, int e) {
    int i = blockIdx.x * blockDim.x + threadIdx.x;
    if (i < e) nrm[i] = dinv[src[i]] * dinv[dst[i]];
}

// ---------------- self-loop init: out[i,:] = in[i,:] * dinv[i]^2 ------------
template <int W4>  // width in float4 (16 for 64-wide, 32 for 128-wide)
__global__ void k_selfinit(const float* __restrict__ in, const float* __restrict__ dinv,
                           float* __restrict__ out, int n) {
    int idx = blockIdx.x * blockDim.x + threadIdx.x;
    if (idx >= n * W4) return;
    int row = idx / W4;
    float dv = dinv[row];
    float s = dv * dv;
    float4 v = reinterpret_cast<const float4*>(in)[idx];
    v.x *= s; v.y *= s; v.z *= s; v.w *= s;
    reinterpret_cast<float4*>(out)[idx] = v;
}

// ---------------- edge scatter: out[dst,:] += feat[src,:] * norm ------------
template <int LOGW4>  // 4 -> 64-wide, 5 -> 128-wide
__global__ void k_scatter(const float* __restrict__ feat, float* __restrict__ out,
                          const int* __restrict__ src, const int* __restrict__ dst,
                          const float* __restrict__ nrm, int e) {
    int idx = blockIdx.x * blockDim.x + threadIdx.x;
    int ee = idx >> LOGW4;
    if (ee >= e) return;
    int j = idx & ((1 << LOGW4) - 1);
    int s = src[ee];
    int d = dst[ee];
    float nm = nrm[ee];
    float4 v = reinterpret_cast<const float4*>(feat)[((size_t)s << LOGW4) + j];
    v.x *= nm; v.y *= nm; v.z *= nm; v.w *= nm;
    float* p = out + ((((size_t)d << LOGW4) + j) << 2);
    asm volatile("red.global.add.v4.f32 [%0], {%1,%2,%3,%4};"
                 :: "l"(p), "f"(v.x), "f"(v.y), "f"(v.z), "f"(v.w) : "memory");
}

// ---------------- fused GEMM + bias + LayerNorm (+ReLU) ---------------------
// out[n,128] = LN(in[n,K] @ W[K,128] + b) * gamma + beta, optional relu.
// Block: 256 threads = 8 warps, 32 rows per block, warp w -> rows 4w..4w+3,
// lane l -> columns 4l..4l+3. N (=100000) is divisible by 32.
template <int K, bool RELU>
__global__ void k_gemm_ln(const float* __restrict__ in, const float* __restrict__ W,
                          const float* __restrict__ bias, const float* __restrict__ gamma,
                          const float* __restrict__ beta, float* __restrict__ out, int nrows) {
    __shared__ float sW[32][128];    // k-tile x 128 cols
    __shared__ float sX[32][33];     // 32 rows x 32 k (+pad)

    const int tid  = threadIdx.x;
    const int warp = tid >> 5;
    const int lane = tid & 31;
    const int row0 = blockIdx.x * 32;
    if (row0 >= nrows) return;

    float acc[4][4];
#pragma unroll
    for (int r = 0; r < 4; r++)
#pragma unroll
        for (int c = 0; c < 4; c++) acc[r][c] = 0.0f;

    for (int kt = 0; kt < K; kt += 32) {
        // W tile: 32x128 floats = 1024 float4, 256 threads -> 4 each
#pragma unroll
        for (int i = tid; i < 1024; i += 256) {
            int kk = i >> 5;
            int c4 = i & 31;
            reinterpret_cast<float4*>(sW[kk])[c4] =
                reinterpret_cast<const float4*>(W + (kt + kk) * 128)[c4];
        }
        // X tile: 32 rows x 32 k = 256 float4, 1 per thread
        {
            int r  = tid >> 3;
            int k4 = tid & 7;
            float4 v = reinterpret_cast<const float4*>(in + (size_t)(row0 + r) * K + kt)[k4];
            sX[r][k4 * 4 + 0] = v.x;
            sX[r][k4 * 4 + 1] = v.y;
            sX[r][k4 * 4 + 2] = v.z;
            sX[r][k4 * 4 + 3] = v.w;
        }
        __syncthreads();

#pragma unroll
        for (int kk = 0; kk < 32; kk++) {
            float4 w = reinterpret_cast<float4*>(sW[kk])[lane];
#pragma unroll
            for (int r = 0; r < 4; r++) {
                float xv = sX[warp * 4 + r][kk];
                acc[r][0] = fmaf(xv, w.x, acc[r][0]);
                acc[r][1] = fmaf(xv, w.y, acc[r][1]);
                acc[r][2] = fmaf(xv, w.z, acc[r][2]);
                acc[r][3] = fmaf(xv, w.w, acc[r][3]);
            }
        }
        __syncthreads();
    }

    const float4 bv = reinterpret_cast<const float4*>(bias)[lane];
    const float4 gv = reinterpret_cast<const float4*>(gamma)[lane];
    const float4 be = reinterpret_cast<const float4*>(beta)[lane];

#pragma unroll
    for (int r = 0; r < 4; r++) {
        float hx = acc[r][0] + bv.x;
        float hy = acc[r][1] + bv.y;
        float hz = acc[r][2] + bv.z;
        float hw = acc[r][3] + bv.w;
        // mean
        float s = hx + hy + hz + hw;
#pragma unroll
        for (int o = 16; o > 0; o >>= 1) s += __shfl_xor_sync(0xffffffffu, s, o);
        float mu = s * (1.0f / 128.0f);
        float dx = hx - mu, dy = hy - mu, dz = hz - mu, dw = hw - mu;
        float q = dx * dx + dy * dy + dz * dz + dw * dw;
#pragma unroll
        for (int o = 16; o > 0; o >>= 1) q += __shfl_xor_sync(0xffffffffu, q, o);
        float rstd = rsqrtf(q * (1.0f / 128.0f) + LN_EPS);

        float4 o4;
        o4.x = dx * rstd * gv.x + be.x;
        o4.y = dy * rstd * gv.y + be.y;
        o4.z = dz * rstd * gv.z + be.z;
        o4.w = dw * rstd * gv.w + be.w;
        if (RELU) {
            o4.x = fmaxf(o4.x, 0.0f);
            o4.y = fmaxf(o4.y, 0.0f);
            o4.z = fmaxf(o4.z, 0.0f);
            o4.w = fmaxf(o4.w, 0.0f);
        }
        int row = row0 + warp * 4 + r;
        reinterpret_cast<float4*>(out + (size_t)row * 128)[lane] = o4;
    }
}

// ---------------- pooling ----------------
__global__ void k_zero_pool(float* gsum, int* gcnt) {
    int i = blockIdx.x * blockDim.x + threadIdx.x;
    if (i < NGRAPH * HDIM) gsum[i] = 0.0f;
    if (i < NGRAPH) gcnt[i] = 0;
}
__global__ void k_count_nodes(const int* __restrict__ batch, int* gcnt, int n) {
    int i = blockIdx.x * blockDim.x + threadIdx.x;
    if (i < n) atomicAdd(&gcnt[batch[i]], 1);
}
// batch is sorted: accumulate slabs in registers, flush only on graph change.
__global__ void k_pool_sum(const float* __restrict__ h, const int* __restrict__ batch,
                           float* __restrict__ gsum, int n, int rpb) {
    int c  = threadIdx.x;  // 0..127
    int r0 = blockIdx.x * rpb;
    int r1 = min(r0 + rpb, n);
    if (r0 >= r1) return;
    float acc = 0.0f;
    int cur = batch[r0];
    for (int r = r0; r < r1; r++) {
        int g = batch[r];
        if (g != cur) {
            atomicAdd(&gsum[cur * HDIM + c], acc);
            acc = 0.0f;
            cur = g;
        }
        acc += h[(size_t)r * HDIM + c];
    }
    atomicAdd(&gsum[cur * HDIM + c], acc);
}
__global__ void k_finalize(const float* __restrict__ gsum, const int* __restrict__ gcnt,
                           float* __restrict__ out) {
    int i = blockIdx.x * blockDim.x + threadIdx.x;
    if (i >= NGRAPH * HDIM) return;
    float cnt = fmaxf((float)gcnt[i >> 7], 1.0f);
    out[i] = gsum[i] / cnt;
}

// ---------------- launch ----------------
extern "C" void kernel_launch(void* const* d_in, const int* in_sizes, int n_in,
                              void* d_out, int out_size) {
    const float* x     = (const float*)d_in[0];
    const int*   eidx  = (const int*)d_in[1];
    const int*   batch = (const int*)d_in[2];
    const float* W1 = (const float*)d_in[3];
    const float* b1 = (const float*)d_in[4];
    const float* g1 = (const float*)d_in[5];
    const float* be1 = (const float*)d_in[6];
    const float* W2 = (const float*)d_in[7];
    const float* b2 = (const float*)d_in[8];
    const float* g2 = (const float*)d_in[9];
    const float* be2 = (const float*)d_in[10];

    const int n = in_sizes[0] / FDIM;   // 100000
    const int e = in_sizes[1] / 2;      // 1600000
    const int* src = eidx;
    const int* dst = eidx + e;

    float* dinv; cudaGetSymbolAddress((void**)&dinv, g_dinv);
    float* nrm;  cudaGetSymbolAddress((void**)&nrm,  g_norm);
    float* bufa; cudaGetSymbolAddress((void**)&bufa, g_bufa);
    float* bufb; cudaGetSymbolAddress((void**)&bufb, g_bufb);
    float* gsum; cudaGetSymbolAddress((void**)&gsum, g_gsum);
    int*   gcnt; cudaGetSymbolAddress((void**)&gcnt, g_gcnt);

    const int T = 256;
    auto cdiv = [](int a, int b) { return (a + b - 1) / b; };

    // degree / dinv / per-edge norm (shared by both convs)
    k_init_deg<<<cdiv(n, T), T>>>(dinv, n);
    k_count_deg<<<cdiv(e, T), T>>>(dst, dinv, e);
    k_dinv<<<cdiv(n, T), T>>>(dinv, n);
    k_norm<<<cdiv(e, T), T>>>(src, dst, dinv, nrm, e);

    // conv1: aggregate x (64-wide) BEFORE the GEMM (Agg(xW) == Agg(x)W)
    k_selfinit<16><<<cdiv(n * 16, T), T>>>(x, dinv, bufa, n);
    k_scatter<4><<<cdiv(e * 16, T), T>>>(x, bufa, src, dst, nrm, e);
    k_gemm_ln<FDIM, true><<<n / 32, T>>>(bufa, W1, b1, g1, be1, bufb, n);

    // conv2: aggregate h1 (128-wide), then GEMM+LN
    k_selfinit<32><<<cdiv(n * 32, T), T>>>(bufb, dinv, bufa, n);
    k_scatter<5><<<cdiv(e * 32, T), T>>>(bufb, bufa, src, dst, nrm, e);
    k_gemm_ln<HDIM, false><<<n / 32, T>>>(bufa, W2, b2, g2, be2, bufb, n);

    // mean pool per graph (batch is sorted)
    k_zero_pool<<<cdiv(NGRAPH * HDIM, T), T>>>(gsum, gcnt);
    k_count_nodes<<<cdiv(n, T), T>>>(batch, gcnt, n);
    const int rpb = 128;
    k_pool_sum<<<cdiv(n, rpb), HDIM>>>(bufb, batch, gsum, n, rpb);
    k_finalize<<<cdiv(NGRAPH * HDIM, HDIM), HDIM>>>(gsum, gcnt, (float*)d_out);
}

// round 3
// speedup vs baseline: 1.6064x; 1.6064x over previous
#include <cuda_runtime.h>

// Problem constants (shapes fixed by the dataset)
#define NNODES 100000
#define NEDGES 1600000
#define NGRAPH 128
#define HDIM   128
#define FDIM   64
#define LN_EPS 1e-5f

#define SCANW   1024
#define NSCANBLK ((NNODES + SCANW) / SCANW + 1)   // covers index n inclusive
#define NPARTIAL (NSCANBLK * SCANW)

// ---------------- scratch (device globals; no allocations allowed) ----------
__device__ int   g_deg[NPARTIAL];                   // int degree (no self loop)
__device__ int   g_cnt2[NNODES];                    // fill cursors
__device__ int   g_partial[NPARTIAL];               // per-block exclusive scan
__device__ int   g_blocksum[256];
__device__ int   g_blockpref[256];
__device__ float g_dinv[NNODES];
__device__ int2  g_csr[NEDGES];                     // (src, bits(dinv[src]))
__device__ float g_bufa[(size_t)NNODES * HDIM];
__device__ float g_bufb[(size_t)NNODES * HDIM];
__device__ float g_gsum[NGRAPH * HDIM];
__device__ int   g_gcnt[NGRAPH];

// ---------------- degree count ----------------
__global__ void k_count_deg(const int* __restrict__ dst, int* __restrict__ deg, int e) {
    int i = blockIdx.x * blockDim.x + threadIdx.x;
    if (i < e) atomicAdd(&deg[dst[i]], 1);
}

// ---------------- two-level exclusive scan ----------------
__global__ void k_scan_block(const int* __restrict__ deg, int* __restrict__ partial,
                             int* __restrict__ blocksum, int n) {
    __shared__ int sm[2][SCANW];
    int t = threadIdx.x;
    int g = blockIdx.x * SCANW + t;
    int v = (g < n) ? deg[g] : 0;
    sm[0][t] = v;
    __syncthreads();
    int cur = 0;
#pragma unroll
    for (int off = 1; off < SCANW; off <<= 1) {
        int x = sm[cur][t];
        if (t >= off) x += sm[cur][t - off];
        sm[cur ^ 1][t] = x;
        __syncthreads();
        cur ^= 1;
    }
    int inc = sm[cur][t];
    partial[g] = inc - v;                 // exclusive within block
    if (t == SCANW - 1) blocksum[blockIdx.x] = inc;
}

__global__ void k_scan_carry(const int* __restrict__ blocksum, int* __restrict__ blockpref, int B) {
    __shared__ int sm[2][256];
    int t = threadIdx.x;                  // 256 threads
    int v = (t < B) ? blocksum[t] : 0;
    sm[0][t] = v;
    __syncthreads();
    int cur = 0;
#pragma unroll
    for (int off = 1; off < 256; off <<= 1) {
        int x = sm[cur][t];
        if (t >= off) x += sm[cur][t - off];
        sm[cur ^ 1][t] = x;
        __syncthreads();
        cur ^= 1;
    }
    blockpref[t] = sm[cur][t] - v;        // exclusive across blocks
}

__global__ void k_dinv(const int* __restrict__ deg, float* __restrict__ dinv, int n) {
    int i = blockIdx.x * blockDim.x + threadIdx.x;
    if (i < n) dinv[i] = rsqrtf((float)(deg[i] + 1));   // +1 self loop
}

// ---------------- CSR fill: csr[pos] = (src, dinv[src]) ordered by dst ------
__global__ void k_fill(const int* __restrict__ src, const int* __restrict__ dst,
                       const float* __restrict__ dinv,
                       const int* __restrict__ partial, const int* __restrict__ blockpref,
                       int* __restrict__ cnt2, int2* __restrict__ csr, int e) {
    int i = blockIdx.x * blockDim.x + threadIdx.x;
    if (i >= e) return;
    int s = src[i];
    int d = dst[i];
    int pos = partial[d] + blockpref[d >> 10] + atomicAdd(&cnt2[d], 1);
    csr[pos] = make_int2(s, __float_as_int(dinv[s]));
}

// ---------------- gather aggregation: warp per dst node ---------------------
// out[v] = dinv[v] * ( sum_{s in N(v)} dinv[s]*feat[s] + dinv[v]*feat[v] )
__global__ void __launch_bounds__(256)
k_agg64(const float* __restrict__ feat, const float* __restrict__ dinv,
        const int2* __restrict__ csr, const int* __restrict__ partial,
        const int* __restrict__ blockpref, float* __restrict__ out, int n) {
    int w = (blockIdx.x * blockDim.x + threadIdx.x) >> 5;
    if (w >= n) return;
    int lane = threadIdx.x & 31;
    int r0 = partial[w] + blockpref[w >> 10];
    int r1 = partial[w + 1] + blockpref[(w + 1) >> 10];
    float dv = dinv[w];

    float2 acc = reinterpret_cast<const float2*>(feat)[(size_t)w * 32 + lane];
    acc.x *= dv; acc.y *= dv;

    int r = r0;
    for (; r + 4 <= r1; r += 4) {
        int2 e0 = csr[r], e1 = csr[r + 1], e2 = csr[r + 2], e3 = csr[r + 3];
        float2 v0 = reinterpret_cast<const float2*>(feat)[(size_t)e0.x * 32 + lane];
        float2 v1 = reinterpret_cast<const float2*>(feat)[(size_t)e1.x * 32 + lane];
        float2 v2 = reinterpret_cast<const float2*>(feat)[(size_t)e2.x * 32 + lane];
        float2 v3 = reinterpret_cast<const float2*>(feat)[(size_t)e3.x * 32 + lane];
        float w0 = __int_as_float(e0.y), w1 = __int_as_float(e1.y);
        float w2 = __int_as_float(e2.y), w3 = __int_as_float(e3.y);
        acc.x = fmaf(w0, v0.x, acc.x); acc.y = fmaf(w0, v0.y, acc.y);
        acc.x = fmaf(w1, v1.x, acc.x); acc.y = fmaf(w1, v1.y, acc.y);
        acc.x = fmaf(w2, v2.x, acc.x); acc.y = fmaf(w2, v2.y, acc.y);
        acc.x = fmaf(w3, v3.x, acc.x); acc.y = fmaf(w3, v3.y, acc.y);
    }
    for (; r < r1; r++) {
        int2 e0 = csr[r];
        float2 v0 = reinterpret_cast<const float2*>(feat)[(size_t)e0.x * 32 + lane];
        float w0 = __int_as_float(e0.y);
        acc.x = fmaf(w0, v0.x, acc.x); acc.y = fmaf(w0, v0.y, acc.y);
    }
    acc.x *= dv; acc.y *= dv;
    reinterpret_cast<float2*>(out)[(size_t)w * 32 + lane] = acc;
}

__global__ void __launch_bounds__(256)
k_agg128(const float* __restrict__ feat, const float* __restrict__ dinv,
         const int2* __restrict__ csr, const int* __restrict__ partial,
         const int* __restrict__ blockpref, float* __restrict__ out, int n) {
    int w = (blockIdx.x * blockDim.x + threadIdx.x) >> 5;
    if (w >= n) return;
    int lane = threadIdx.x & 31;
    int r0 = partial[w] + blockpref[w >> 10];
    int r1 = partial[w + 1] + blockpref[(w + 1) >> 10];
    float dv = dinv[w];

    float4 acc = reinterpret_cast<const float4*>(feat)[(size_t)w * 32 + lane];
    acc.x *= dv; acc.y *= dv; acc.z *= dv; acc.w *= dv;

    int r = r0;
    for (; r + 4 <= r1; r += 4) {
        int2 e0 = csr[r], e1 = csr[r + 1], e2 = csr[r + 2], e3 = csr[r + 3];
        float4 v0 = reinterpret_cast<const float4*>(feat)[(size_t)e0.x * 32 + lane];
        float4 v1 = reinterpret_cast<const float4*>(feat)[(size_t)e1.x * 32 + lane];
        float4 v2 = reinterpret_cast<const float4*>(feat)[(size_t)e2.x * 32 + lane];
        float4 v3 = reinterpret_cast<const float4*>(feat)[(size_t)e3.x * 32 + lane];
        float w0 = __int_as_float(e0.y), w1 = __int_as_float(e1.y);
        float w2 = __int_as_float(e2.y), w3 = __int_as_float(e3.y);
        acc.x = fmaf(w0, v0.x, acc.x); acc.y = fmaf(w0, v0.y, acc.y);
        acc.z = fmaf(w0, v0.z, acc.z); acc.w = fmaf(w0, v0.w, acc.w);
        acc.x = fmaf(w1, v1.x, acc.x); acc.y = fmaf(w1, v1.y, acc.y);
        acc.z = fmaf(w1, v1.z, acc.z); acc.w = fmaf(w1, v1.w, acc.w);
        acc.x = fmaf(w2, v2.x, acc.x); acc.y = fmaf(w2, v2.y, acc.y);
        acc.z = fmaf(w2, v2.z, acc.z); acc.w = fmaf(w2, v2.w, acc.w);
        acc.x = fmaf(w3, v3.x, acc.x); acc.y = fmaf(w3, v3.y, acc.y);
        acc.z = fmaf(w3, v3.z, acc.z); acc.w = fmaf(w3, v3.w, acc.w);
    }
    for (; r < r1; r++) {
        int2 e0 = csr[r];
        float4 v0 = reinterpret_cast<const float4*>(feat)[(size_t)e0.x * 32 + lane];
        float w0 = __int_as_float(e0.y);
        acc.x = fmaf(w0, v0.x, acc.x); acc.y = fmaf(w0, v0.y, acc.y);
        acc.z = fmaf(w0, v0.z, acc.z); acc.w = fmaf(w0, v0.w, acc.w);
    }
    acc.x *= dv; acc.y *= dv; acc.z *= dv; acc.w *= dv;
    reinterpret_cast<float4*>(out)[(size_t)w * 32 + lane] = acc;
}

// ---------------- fused GEMM + bias + LayerNorm (+ReLU) ---------------------
template <int K, bool RELU>
__global__ void k_gemm_ln(const float* __restrict__ in, const float* __restrict__ W,
                          const float* __restrict__ bias, const float* __restrict__ gamma,
                          const float* __restrict__ beta, float* __restrict__ out, int nrows) {
    __shared__ float sW[32][128];
    __shared__ float sX[32][33];

    const int tid  = threadIdx.x;
    const int warp = tid >> 5;
    const int lane = tid & 31;
    const int row0 = blockIdx.x * 32;
    if (row0 >= nrows) return;

    float acc[4][4];
#pragma unroll
    for (int r = 0; r < 4; r++)
#pragma unroll
        for (int c = 0; c < 4; c++) acc[r][c] = 0.0f;

    for (int kt = 0; kt < K; kt += 32) {
#pragma unroll
        for (int i = tid; i < 1024; i += 256) {
            int kk = i >> 5;
            int c4 = i & 31;
            reinterpret_cast<float4*>(sW[kk])[c4] =
                reinterpret_cast<const float4*>(W + (kt + kk) * 128)[c4];
        }
        {
            int r  = tid >> 3;
            int k4 = tid & 7;
            float4 v = reinterpret_cast<const float4*>(in + (size_t)(row0 + r) * K + kt)[k4];
            sX[r][k4 * 4 + 0] = v.x;
            sX[r][k4 * 4 + 1] = v.y;
            sX[r][k4 * 4 + 2] = v.z;
            sX[r][k4 * 4 + 3] = v.w;
        }
        __syncthreads();

#pragma unroll
        for (int kk = 0; kk < 32; kk++) {
            float4 w = reinterpret_cast<float4*>(sW[kk])[lane];
#pragma unroll
            for (int r = 0; r < 4; r++) {
                float xv = sX[warp * 4 + r][kk];
                acc[r][0] = fmaf(xv, w.x, acc[r][0]);
                acc[r][1] = fmaf(xv, w.y, acc[r][1]);
                acc[r][2] = fmaf(xv, w.z, acc[r][2]);
                acc[r][3] = fmaf(xv, w.w, acc[r][3]);
            }
        }
        __syncthreads();
    }

    const float4 bv = reinterpret_cast<const float4*>(bias)[lane];
    const float4 gv = reinterpret_cast<const float4*>(gamma)[lane];
    const float4 be = reinterpret_cast<const float4*>(beta)[lane];

#pragma unroll
    for (int r = 0; r < 4; r++) {
        float hx = acc[r][0] + bv.x;
        float hy = acc[r][1] + bv.y;
        float hz = acc[r][2] + bv.z;
        float hw = acc[r][3] + bv.w;
        float s = hx + hy + hz + hw;
#pragma unroll
        for (int o = 16; o > 0; o >>= 1) s += __shfl_xor_sync(0xffffffffu, s, o);
        float mu = s * (1.0f / 128.0f);
        float dx = hx - mu, dy = hy - mu, dz = hz - mu, dw = hw - mu;
        float q = dx * dx + dy * dy + dz * dz + dw * dw;
#pragma unroll
        for (int o = 16; o > 0; o >>= 1) q += __shfl_xor_sync(0xffffffffu, q, o);
        float rstd = rsqrtf(q * (1.0f / 128.0f) + LN_EPS);

        float4 o4;
        o4.x = dx * rstd * gv.x + be.x;
        o4.y = dy * rstd * gv.y + be.y;
        o4.z = dz * rstd * gv.z + be.z;
        o4.w = dw * rstd * gv.w + be.w;
        if (RELU) {
            o4.x = fmaxf(o4.x, 0.0f);
            o4.y = fmaxf(o4.y, 0.0f);
            o4.z = fmaxf(o4.z, 0.0f);
            o4.w = fmaxf(o4.w, 0.0f);
        }
        int row = row0 + warp * 4 + r;
        reinterpret_cast<float4*>(out + (size_t)row * 128)[lane] = o4;
    }
}

// ---------------- pooling (batch is sorted; count fused) ----------------
__global__ void k_pool_sum(const float* __restrict__ h, const int* __restrict__ batch,
                           float* __restrict__ gsum, int* __restrict__ gcnt, int n, int rpb) {
    int c  = threadIdx.x;  // 0..127
    int r0 = blockIdx.x * rpb;
    int r1 = min(r0 + rpb, n);
    if (r0 >= r1) return;
    float acc = 0.0f;
    int cnt = 0;
    int cur = batch[r0];
    for (int r = r0; r < r1; r++) {
        int g = batch[r];
        if (g != cur) {
            atomicAdd(&gsum[cur * HDIM + c], acc);
            if (c == 0) atomicAdd(&gcnt[cur], cnt);
            acc = 0.0f; cnt = 0; cur = g;
        }
        acc += h[(size_t)r * HDIM + c];
        cnt++;
    }
    atomicAdd(&gsum[cur * HDIM + c], acc);
    if (c == 0) atomicAdd(&gcnt[cur], cnt);
}

__global__ void k_finalize(const float* __restrict__ gsum, const int* __restrict__ gcnt,
                           float* __restrict__ out) {
    int i = blockIdx.x * blockDim.x + threadIdx.x;
    if (i >= NGRAPH * HDIM) return;
    float cnt = fmaxf((float)gcnt[i >> 7], 1.0f);
    out[i] = gsum[i] / cnt;
}

// ---------------- launch ----------------
extern "C" void kernel_launch(void* const* d_in, const int* in_sizes, int n_in,
                              void* d_out, int out_size) {
    const float* x     = (const float*)d_in[0];
    const int*   eidx  = (const int*)d_in[1];
    const int*   batch = (const int*)d_in[2];
    const float* W1 = (const float*)d_in[3];
    const float* b1 = (const float*)d_in[4];
    const float* g1 = (const float*)d_in[5];
    const float* be1 = (const float*)d_in[6];
    const float* W2 = (const float*)d_in[7];
    const float* b2 = (const float*)d_in[8];
    const float* g2 = (const float*)d_in[9];
    const float* be2 = (const float*)d_in[10];

    const int n = in_sizes[0] / FDIM;   // 100000
    const int e = in_sizes[1] / 2;      // 1600000
    const int* src = eidx;
    const int* dst = eidx + e;

    int*   deg;   cudaGetSymbolAddress((void**)&deg,   g_deg);
    int*   cnt2;  cudaGetSymbolAddress((void**)&cnt2,  g_cnt2);
    int*   part;  cudaGetSymbolAddress((void**)&part,  g_partial);
    int*   bsum;  cudaGetSymbolAddress((void**)&bsum,  g_blocksum);
    int*   bpref; cudaGetSymbolAddress((void**)&bpref, g_blockpref);
    float* dinv;  cudaGetSymbolAddress((void**)&dinv,  g_dinv);
    int2*  csr;   cudaGetSymbolAddress((void**)&csr,   g_csr);
    float* bufa;  cudaGetSymbolAddress((void**)&bufa,  g_bufa);
    float* bufb;  cudaGetSymbolAddress((void**)&bufb,  g_bufb);
    float* gsum;  cudaGetSymbolAddress((void**)&gsum,  g_gsum);
    int*   gcnt;  cudaGetSymbolAddress((void**)&gcnt,  g_gcnt);

    const int T = 256;
    auto cdiv = [](int a, int b) { return (a + b - 1) / b; };
    const int B = cdiv(n + 1, SCANW);   // scan blocks (covers index n)

    // CSR build (shared by both convs)
    cudaMemsetAsync(deg, 0, sizeof(int) * NPARTIAL);
    cudaMemsetAsync(cnt2, 0, sizeof(int) * NNODES);
    k_count_deg<<<cdiv(e, T), T>>>(dst, deg, e);
    k_scan_block<<<B, SCANW>>>(deg, part, bsum, n);
    k_scan_carry<<<1, 256>>>(bsum, bpref, B);
    k_dinv<<<cdiv(n, T), T>>>(deg, dinv, n);
    k_fill<<<cdiv(e, T), T>>>(src, dst, dinv, part, bpref, cnt2, csr, e);

    // conv1: gather-aggregate x (64-wide) then GEMM (Agg(xW) == Agg(x)W)
    k_agg64<<<cdiv(n * 32, T), T>>>(x, dinv, csr, part, bpref, bufa, n);
    k_gemm_ln<FDIM, true><<<n / 32, T>>>(bufa, W1, b1, g1, be1, bufb, n);

    // conv2: gather-aggregate h1 (128-wide) then GEMM+LN
    k_agg128<<<cdiv(n * 32, T), T>>>(bufb, dinv, csr, part, bpref, bufa, n);
    k_gemm_ln<HDIM, false><<<n / 32, T>>>(bufa, W2, b2, g2, be2, bufb, n);

    // mean pool per graph (batch is sorted)
    cudaMemsetAsync(gsum, 0, sizeof(float) * NGRAPH * HDIM);
    cudaMemsetAsync(gcnt, 0, sizeof(int) * NGRAPH);
    const int rpb = 128;
    k_pool_sum<<<cdiv(n, rpb), HDIM>>>(bufb, batch, gsum, gcnt, n, rpb);
    k_finalize<<<cdiv(NGRAPH * HDIM, HDIM), HDIM>>>(gsum, gcnt, (float*)d_out);
}

// round 4
// speedup vs baseline: 1.6609x; 1.0339x over previous
#include <cuda_runtime.h>

// Problem constants (shapes fixed by the dataset)
#define NNODES 100000
#define NEDGES 1600000
#define NGRAPH 128
#define HDIM   128
#define FDIM   64
#define LN_EPS 1e-5f

#define SCANW   1024
#define NSCANBLK ((NNODES + SCANW) / SCANW + 1)   // covers index n inclusive
#define NPARTIAL (NSCANBLK * SCANW)

// ---------------- scratch (device globals; no allocations allowed) ----------
// deg (int counts, no self-loop) followed by fill cursors -> single memset.
__device__ int   g_ibuf[NPARTIAL + NNODES];
__device__ int   g_partial[NPARTIAL];               // per-block exclusive scan
__device__ int   g_blocksum[256];
__device__ int   g_blockpref[256];
__device__ int2  g_csr[NEDGES];                     // (src, bits(dinv[src]))
__device__ float g_bufa[(size_t)NNODES * HDIM];
__device__ float g_bufb[(size_t)NNODES * HDIM];
__device__ float g_pool[NGRAPH * HDIM + NGRAPH];    // gsum then gcnt(int) -> single memset

// ---------------- degree count ----------------
__global__ void k_count_deg(const int* __restrict__ dst, int* __restrict__ deg, int e) {
    int i = blockIdx.x * blockDim.x + threadIdx.x;
    if (i < e) atomicAdd(&deg[dst[i]], 1);
}

// ---------------- two-level exclusive scan ----------------
__global__ void k_scan_block(const int* __restrict__ deg, int* __restrict__ partial,
                             int* __restrict__ blocksum, int n) {
    __shared__ int sm[2][SCANW];
    int t = threadIdx.x;
    int g = blockIdx.x * SCANW + t;
    int v = (g < n) ? deg[g] : 0;
    sm[0][t] = v;
    __syncthreads();
    int cur = 0;
#pragma unroll
    for (int off = 1; off < SCANW; off <<= 1) {
        int x = sm[cur][t];
        if (t >= off) x += sm[cur][t - off];
        sm[cur ^ 1][t] = x;
        __syncthreads();
        cur ^= 1;
    }
    int inc = sm[cur][t];
    partial[g] = inc - v;                 // exclusive within block
    if (t == SCANW - 1) blocksum[blockIdx.x] = inc;
}

__global__ void k_scan_carry(const int* __restrict__ blocksum, int* __restrict__ blockpref, int B) {
    __shared__ int sm[2][256];
    int t = threadIdx.x;                  // 256 threads
    int v = (t < B) ? blocksum[t] : 0;
    sm[0][t] = v;
    __syncthreads();
    int cur = 0;
#pragma unroll
    for (int off = 1; off < 256; off <<= 1) {
        int x = sm[cur][t];
        if (t >= off) x += sm[cur][t - off];
        sm[cur ^ 1][t] = x;
        __syncthreads();
        cur ^= 1;
    }
    blockpref[t] = sm[cur][t] - v;        // exclusive across blocks
}

// ---------------- CSR fill: csr[pos] = (src, dinv[src]) ordered by dst ------
// dinv computed inline from deg (deg excludes self-loop -> +1).
__global__ void k_fill(const int* __restrict__ src, const int* __restrict__ dst,
                       const int* __restrict__ deg,
                       const int* __restrict__ partial, const int* __restrict__ blockpref,
                       int* __restrict__ cnt2, int2* __restrict__ csr, int e) {
    int i = blockIdx.x * blockDim.x + threadIdx.x;
    if (i >= e) return;
    int s = src[i];
    int d = dst[i];
    float dvs = rsqrtf((float)(deg[s] + 1));
    int pos = partial[d] + blockpref[d >> 10] + atomicAdd(&cnt2[d], 1);
    csr[pos] = make_int2(s, __float_as_int(dvs));
}

// ---------------- gather aggregation: warp per dst node ---------------------
// out[v] = dinv[v] * ( sum_{s in N(v)} dinv[s]*feat[s] + dinv[v]*feat[v] )
__global__ void __launch_bounds__(256)
k_agg64(const float* __restrict__ feat, const int* __restrict__ deg,
        const int2* __restrict__ csr, const int* __restrict__ partial,
        const int* __restrict__ blockpref, float* __restrict__ out, int n) {
    int w = (blockIdx.x * blockDim.x + threadIdx.x) >> 5;
    if (w >= n) return;
    int lane = threadIdx.x & 31;
    int r0 = partial[w] + blockpref[w >> 10];
    int r1 = partial[w + 1] + blockpref[(w + 1) >> 10];
    float dv = rsqrtf((float)(deg[w] + 1));

    float2 acc = reinterpret_cast<const float2*>(feat)[(size_t)w * 32 + lane];
    acc.x *= dv; acc.y *= dv;

    int r = r0;
    for (; r + 4 <= r1; r += 4) {
        int2 e0 = csr[r], e1 = csr[r + 1], e2 = csr[r + 2], e3 = csr[r + 3];
        float2 v0 = reinterpret_cast<const float2*>(feat)[(size_t)e0.x * 32 + lane];
        float2 v1 = reinterpret_cast<const float2*>(feat)[(size_t)e1.x * 32 + lane];
        float2 v2 = reinterpret_cast<const float2*>(feat)[(size_t)e2.x * 32 + lane];
        float2 v3 = reinterpret_cast<const float2*>(feat)[(size_t)e3.x * 32 + lane];
        float w0 = __int_as_float(e0.y), w1 = __int_as_float(e1.y);
        float w2 = __int_as_float(e2.y), w3 = __int_as_float(e3.y);
        acc.x = fmaf(w0, v0.x, acc.x); acc.y = fmaf(w0, v0.y, acc.y);
        acc.x = fmaf(w1, v1.x, acc.x); acc.y = fmaf(w1, v1.y, acc.y);
        acc.x = fmaf(w2, v2.x, acc.x); acc.y = fmaf(w2, v2.y, acc.y);
        acc.x = fmaf(w3, v3.x, acc.x); acc.y = fmaf(w3, v3.y, acc.y);
    }
    for (; r < r1; r++) {
        int2 e0 = csr[r];
        float2 v0 = reinterpret_cast<const float2*>(feat)[(size_t)e0.x * 32 + lane];
        float w0 = __int_as_float(e0.y);
        acc.x = fmaf(w0, v0.x, acc.x); acc.y = fmaf(w0, v0.y, acc.y);
    }
    acc.x *= dv; acc.y *= dv;
    reinterpret_cast<float2*>(out)[(size_t)w * 32 + lane] = acc;
}

__global__ void __launch_bounds__(256)
k_agg128(const float* __restrict__ feat, const int* __restrict__ deg,
         const int2* __restrict__ csr, const int* __restrict__ partial,
         const int* __restrict__ blockpref, float* __restrict__ out, int n) {
    int w = (blockIdx.x * blockDim.x + threadIdx.x) >> 5;
    if (w >= n) return;
    int lane = threadIdx.x & 31;
    int r0 = partial[w] + blockpref[w >> 10];
    int r1 = partial[w + 1] + blockpref[(w + 1) >> 10];
    float dv = rsqrtf((float)(deg[w] + 1));

    float4 acc = reinterpret_cast<const float4*>(feat)[(size_t)w * 32 + lane];
    acc.x *= dv; acc.y *= dv; acc.z *= dv; acc.w *= dv;

    int r = r0;
    for (; r + 4 <= r1; r += 4) {
        int2 e0 = csr[r], e1 = csr[r + 1], e2 = csr[r + 2], e3 = csr[r + 3];
        float4 v0 = reinterpret_cast<const float4*>(feat)[(size_t)e0.x * 32 + lane];
        float4 v1 = reinterpret_cast<const float4*>(feat)[(size_t)e1.x * 32 + lane];
        float4 v2 = reinterpret_cast<const float4*>(feat)[(size_t)e2.x * 32 + lane];
        float4 v3 = reinterpret_cast<const float4*>(feat)[(size_t)e3.x * 32 + lane];
        float w0 = __int_as_float(e0.y), w1 = __int_as_float(e1.y);
        float w2 = __int_as_float(e2.y), w3 = __int_as_float(e3.y);
        acc.x = fmaf(w0, v0.x, acc.x); acc.y = fmaf(w0, v0.y, acc.y);
        acc.z = fmaf(w0, v0.z, acc.z); acc.w = fmaf(w0, v0.w, acc.w);
        acc.x = fmaf(w1, v1.x, acc.x); acc.y = fmaf(w1, v1.y, acc.y);
        acc.z = fmaf(w1, v1.z, acc.z); acc.w = fmaf(w1, v1.w, acc.w);
        acc.x = fmaf(w2, v2.x, acc.x); acc.y = fmaf(w2, v2.y, acc.y);
        acc.z = fmaf(w2, v2.z, acc.z); acc.w = fmaf(w2, v2.w, acc.w);
        acc.x = fmaf(w3, v3.x, acc.x); acc.y = fmaf(w3, v3.y, acc.y);
        acc.z = fmaf(w3, v3.z, acc.z); acc.w = fmaf(w3, v3.w, acc.w);
    }
    for (; r < r1; r++) {
        int2 e0 = csr[r];
        float4 v0 = reinterpret_cast<const float4*>(feat)[(size_t)e0.x * 32 + lane];
        float w0 = __int_as_float(e0.y);
        acc.x = fmaf(w0, v0.x, acc.x); acc.y = fmaf(w0, v0.y, acc.y);
        acc.z = fmaf(w0, v0.z, acc.z); acc.w = fmaf(w0, v0.w, acc.w);
    }
    acc.x *= dv; acc.y *= dv; acc.z *= dv; acc.w *= dv;
    reinterpret_cast<float4*>(out)[(size_t)w * 32 + lane] = acc;
}

// ---------------- fused GEMM + bias + LayerNorm (+ReLU) ---------------------
// X tile stored TRANSPOSED (sXT[k][row]) so the 4 row-operands per thread are
// one broadcast LDS.128 -> inner loop is 2 LDS.128 + 16 FFMA per k.
template <int K, bool RELU>
__global__ void __launch_bounds__(256)
k_gemm_ln(const float* __restrict__ in, const float* __restrict__ W,
          const float* __restrict__ bias, const float* __restrict__ gamma,
          const float* __restrict__ beta, float* __restrict__ out, int nrows) {
    __shared__ __align__(16) float sW[32][128];
    __shared__ __align__(16) float sXT[32][36];   // [k][row], stride 36 keeps 16B align

    const int tid  = threadIdx.x;
    const int warp = tid >> 5;
    const int lane = tid & 31;
    const int row0 = blockIdx.x * 32;
    if (row0 >= nrows) return;

    float acc[4][4];
#pragma unroll
    for (int r = 0; r < 4; r++)
#pragma unroll
        for (int c = 0; c < 4; c++) acc[r][c] = 0.0f;

#pragma unroll
    for (int kt = 0; kt < K; kt += 32) {
        // W tile: 32x128 floats = 1024 float4, 256 threads -> 4 each
#pragma unroll
        for (int i = tid; i < 1024; i += 256) {
            int kk = i >> 5;
            int c4 = i & 31;
            reinterpret_cast<float4*>(sW[kk])[c4] =
                reinterpret_cast<const float4*>(W + (size_t)(kt + kk) * 128)[c4];
        }
        // X tile transposed: thread t loads row r=t>>3, k-chunk k4=t&7 (float4)
        {
            int r  = tid >> 3;
            int k4 = tid & 7;
            float4 v = reinterpret_cast<const float4*>(in + (size_t)(row0 + r) * K + kt)[k4];
            sXT[k4 * 4 + 0][r] = v.x;
            sXT[k4 * 4 + 1][r] = v.y;
            sXT[k4 * 4 + 2][r] = v.z;
            sXT[k4 * 4 + 3][r] = v.w;
        }
        __syncthreads();

#pragma unroll
        for (int kk = 0; kk < 32; kk++) {
            float4 wv = reinterpret_cast<float4*>(sW[kk])[lane];
            float4 xv = *reinterpret_cast<float4*>(&sXT[kk][warp * 4]);   // broadcast
            acc[0][0] = fmaf(xv.x, wv.x, acc[0][0]);
            acc[0][1] = fmaf(xv.x, wv.y, acc[0][1]);
            acc[0][2] = fmaf(xv.x, wv.z, acc[0][2]);
            acc[0][3] = fmaf(xv.x, wv.w, acc[0][3]);
            acc[1][0] = fmaf(xv.y, wv.x, acc[1][0]);
            acc[1][1] = fmaf(xv.y, wv.y, acc[1][1]);
            acc[1][2] = fmaf(xv.y, wv.z, acc[1][2]);
            acc[1][3] = fmaf(xv.y, wv.w, acc[1][3]);
            acc[2][0] = fmaf(xv.z, wv.x, acc[2][0]);
            acc[2][1] = fmaf(xv.z, wv.y, acc[2][1]);
            acc[2][2] = fmaf(xv.z, wv.z, acc[2][2]);
            acc[2][3] = fmaf(xv.z, wv.w, acc[2][3]);
            acc[3][0] = fmaf(xv.w, wv.x, acc[3][0]);
            acc[3][1] = fmaf(xv.w, wv.y, acc[3][1]);
            acc[3][2] = fmaf(xv.w, wv.z, acc[3][2]);
            acc[3][3] = fmaf(xv.w, wv.w, acc[3][3]);
        }
        __syncthreads();
    }

    const float4 bv = reinterpret_cast<const float4*>(bias)[lane];
    const float4 gv = reinterpret_cast<const float4*>(gamma)[lane];
    const float4 be = reinterpret_cast<const float4*>(beta)[lane];

#pragma unroll
    for (int r = 0; r < 4; r++) {
        float hx = acc[r][0] + bv.x;
        float hy = acc[r][1] + bv.y;
        float hz = acc[r][2] + bv.z;
        float hw = acc[r][3] + bv.w;
        float s = hx + hy + hz + hw;
#pragma unroll
        for (int o = 16; o > 0; o >>= 1) s += __shfl_xor_sync(0xffffffffu, s, o);
        float mu = s * (1.0f / 128.0f);
        float dx = hx - mu, dy = hy - mu, dz = hz - mu, dw = hw - mu;
        float q = dx * dx + dy * dy + dz * dz + dw * dw;
#pragma unroll
        for (int o = 16; o > 0; o >>= 1) q += __shfl_xor_sync(0xffffffffu, q, o);
        float rstd = rsqrtf(q * (1.0f / 128.0f) + LN_EPS);

        float4 o4;
        o4.x = dx * rstd * gv.x + be.x;
        o4.y = dy * rstd * gv.y + be.y;
        o4.z = dz * rstd * gv.z + be.z;
        o4.w = dw * rstd * gv.w + be.w;
        if (RELU) {
            o4.x = fmaxf(o4.x, 0.0f);
            o4.y = fmaxf(o4.y, 0.0f);
            o4.z = fmaxf(o4.z, 0.0f);
            o4.w = fmaxf(o4.w, 0.0f);
        }
        int row = row0 + warp * 4 + r;
        reinterpret_cast<float4*>(out + (size_t)row * 128)[lane] = o4;
    }
}

// ---------------- pooling (batch is sorted; count fused) ----------------
__global__ void k_pool_sum(const float* __restrict__ h, const int* __restrict__ batch,
                           float* __restrict__ gsum, int* __restrict__ gcnt, int n, int rpb) {
    int c  = threadIdx.x;  // 0..127
    int r0 = blockIdx.x * rpb;
    int r1 = min(r0 + rpb, n);
    if (r0 >= r1) return;
    float acc = 0.0f;
    int cnt = 0;
    int cur = batch[r0];
    for (int r = r0; r < r1; r++) {
        int g = batch[r];
        if (g != cur) {
            atomicAdd(&gsum[cur * HDIM + c], acc);
            if (c == 0) atomicAdd(&gcnt[cur], cnt);
            acc = 0.0f; cnt = 0; cur = g;
        }
        acc += h[(size_t)r * HDIM + c];
        cnt++;
    }
    atomicAdd(&gsum[cur * HDIM + c], acc);
    if (c == 0) atomicAdd(&gcnt[cur], cnt);
}

__global__ void k_finalize(const float* __restrict__ gsum, const int* __restrict__ gcnt,
                           float* __restrict__ out) {
    int i = blockIdx.x * blockDim.x + threadIdx.x;
    if (i >= NGRAPH * HDIM) return;
    float cnt = fmaxf((float)gcnt[i >> 7], 1.0f);
    out[i] = gsum[i] / cnt;
}

// ---------------- launch ----------------
extern "C" void kernel_launch(void* const* d_in, const int* in_sizes, int n_in,
                              void* d_out, int out_size) {
    const float* x     = (const float*)d_in[0];
    const int*   eidx  = (const int*)d_in[1];
    const int*   batch = (const int*)d_in[2];
    const float* W1 = (const float*)d_in[3];
    const float* b1 = (const float*)d_in[4];
    const float* g1 = (const float*)d_in[5];
    const float* be1 = (const float*)d_in[6];
    const float* W2 = (const float*)d_in[7];
    const float* b2 = (const float*)d_in[8];
    const float* g2 = (const float*)d_in[9];
    const float* be2 = (const float*)d_in[10];

    const int n = in_sizes[0] / FDIM;   // 100000
    const int e = in_sizes[1] / 2;      // 1600000
    const int* src = eidx;
    const int* dst = eidx + e;

    int*   ibuf;  cudaGetSymbolAddress((void**)&ibuf,  g_ibuf);
    int*   part;  cudaGetSymbolAddress((void**)&part,  g_partial);
    int*   bsum;  cudaGetSymbolAddress((void**)&bsum,  g_blocksum);
    int*   bpref; cudaGetSymbolAddress((void**)&bpref, g_blockpref);
    int2*  csr;   cudaGetSymbolAddress((void**)&csr,   g_csr);
    float* bufa;  cudaGetSymbolAddress((void**)&bufa,  g_bufa);
    float* bufb;  cudaGetSymbolAddress((void**)&bufb,  g_bufb);
    float* pool;  cudaGetSymbolAddress((void**)&pool,  g_pool);

    int* deg  = ibuf;
    int* cnt2 = ibuf + NPARTIAL;
    float* gsum = pool;
    int*   gcnt = (int*)(pool + NGRAPH * HDIM);

    const int T = 256;
    auto cdiv = [](int a, int b) { return (a + b - 1) / b; };
    const int B = cdiv(n + 1, SCANW);   // scan blocks (covers index n)

    // CSR build (shared by both convs). Launch order keeps k_agg64 at launch #6
    // so ncu (-s 5 -c 1) profiles it.
    cudaMemsetAsync(ibuf, 0, sizeof(int) * (NPARTIAL + NNODES));        // 1
    k_count_deg<<<cdiv(e, T), T>>>(dst, deg, e);                        // 2
    k_scan_block<<<B, SCANW>>>(deg, part, bsum, n);                     // 3
    k_scan_carry<<<1, 256>>>(bsum, bpref, B);                           // 4
    k_fill<<<cdiv(e, T), T>>>(src, dst, deg, part, bpref, cnt2, csr, e);// 5

    // conv1: gather-aggregate x (64-wide) then GEMM (Agg(xW) == Agg(x)W)
    k_agg64<<<cdiv(n * 32, T), T>>>(x, deg, csr, part, bpref, bufa, n); // 6 <- profiled
    cudaMemsetAsync(pool, 0, sizeof(float) * (NGRAPH * HDIM) + sizeof(int) * NGRAPH);
    k_gemm_ln<FDIM, true><<<n / 32, T>>>(bufa, W1, b1, g1, be1, bufb, n);

    // conv2: gather-aggregate h1 (128-wide) then GEMM+LN
    k_agg128<<<cdiv(n * 32, T), T>>>(bufb, deg, csr, part, bpref, bufa, n);
    k_gemm_ln<HDIM, false><<<n / 32, T>>>(bufa, W2, b2, g2, be2, bufb, n);

    // mean pool per graph (batch is sorted)
    const int rpb = 128;
    k_pool_sum<<<cdiv(n, rpb), HDIM>>>(bufb, batch, gsum, gcnt, n, rpb);
    k_finalize<<<cdiv(NGRAPH * HDIM, HDIM), HDIM>>>(gsum, gcnt, (float*)d_out);
}